// round 16
// baseline (speedup 1.0000x reference)
#include <cuda_runtime.h>
#include <cuda_fp16.h>
#include <mma.h>
#include <cstdint>
#include <cstddef>

using namespace nvcuda;

#define N_NODES 8192
#define IN_C    512
#define HID_C   1024
#define OUT_C   256

// ---------------- scratch (static device arrays; no allocations) ----------------
__device__ float  g_inv [N_NODES];                       // D^{-1/2}
__device__ float  g_asum[N_NODES];                       // rowsum of effective Â
__device__ __half g_Ah  [(size_t)N_NODES * N_NODES];     // fp16(edge), RAW (128 MB)
__device__ __half g_XTh [(size_t)IN_C * N_NODES];        // fp16(inv_n * X^T)
__device__ __half g_W1h [(size_t)HID_C * IN_C];
__device__ __half g_W2h [(size_t)OUT_C * HID_C];
__device__ __half g_Gh  [(size_t)N_NODES * IN_C];        // fp16(Â@X)    (GEMM_a out)
__device__ __half g_Hh  [(size_t)N_NODES * HID_C];       // fp16(hidden) (GEMM_b out)
__device__ __half g_OsTh[(size_t)OUT_C * N_NODES];       // fp16(inv_m * Os^T) (GEMM_c out)

__device__ __forceinline__ uint32_t smem_u32(const void* p) {
    uint32_t a;
    asm("{ .reg .u64 t; cvta.to.shared.u64 t, %1; cvt.u32.u64 %0, t; }" : "=r"(a) : "l"(p));
    return a;
}
__device__ __forceinline__ void cp16(uint32_t dst, const void* src) {
    asm volatile("cp.async.cg.shared.global [%0], [%1], 16;" :: "r"(dst), "l"(src));
}
#define CP_COMMIT() asm volatile("cp.async.commit_group;" ::: "memory")
#define CP_WAIT1()  asm volatile("cp.async.wait_group 1;" ::: "memory")

// ---- fp16 wmma GEMM: 128x128 block, 256 thr, 8 warps of 32x64, 3-stage cp.async,
// ---- 2 CTAs/SM. Fused epilogue modes (all full-K, no split):
//   MODE 1: fp16 store, acc * rv1[m]                         (Gh)
//   MODE 2: fp16 store, relu(acc + rv1[m]*bias[j])           (Hh)
//   MODE 3: fp16 TRANSPOSED store, Cout[n, m] = acc*rv1[m];
//           output row stride = outStride                    (OsTh)
//   MODE 4: fp32 store, relu(rv1[m]*acc + rv2[m]*bias[j])    (final out)
// C[M,Ncols] = A[M,Klen] @ B[Ncols,Klen]^T, fp16 K-major operands.
constexpr int NTHR = 256;
constexpr int BM = 128, BN = 128, BK = 64;                // BK halves = 128 B/row
constexpr int BKP = 72;                                   // 144 B/row padded
constexpr int STAGES = 3;
constexpr int A_STAGE_B = BM * BKP * 2;                   // 18432
constexpr int STAGE_B   = (BM + BN) * BKP * 2;            // 36864
constexpr int SMEM_GEMM = STAGES * STAGE_B;               // 110592 (x2 CTAs = 221184/SM)
constexpr int WMI = 2, WNI = 4;                           // 32x64 warp tile
constexpr int EPI_LD = 132;                               // fp32 scratch stride (mult of 4)

template <int MODE>
__global__ __launch_bounds__(NTHR, 2) void tc_gemm(
    const __half* __restrict__ A, const __half* __restrict__ B,
    void* __restrict__ Cout, int strideA, int strideB,
    int Klen, int Ncols, size_t outStride,
    const float* __restrict__ rv1, const float* __restrict__ rv2,
    const float* __restrict__ bias)
{
    extern __shared__ __align__(16) char smem[];
    __half* sh = reinterpret_cast<__half*>(smem);
    const uint32_t sb = smem_u32(smem);

    const int tid  = threadIdx.x;
    const int warp = tid >> 5;
    const int bm0  = blockIdx.y * BM;
    const int bn0  = blockIdx.x * BN;
    const int wm0 = (warp >> 1) * 32;    // 4 warp rows
    const int wn0 = (warp & 1) * 64;     // 2 warp cols
    const int NKB = Klen / BK;

    wmma::fragment<wmma::accumulator, 16, 16, 16, float> acc[WMI][WNI];
    #pragma unroll
    for (int i = 0; i < WMI; i++)
        #pragma unroll
        for (int j = 0; j < WNI; j++)
            wmma::fill_fragment(acc[i][j], 0.f);

    const __half* Abase = A + (size_t)bm0 * strideA;
    const __half* Bbase = B + (size_t)bn0 * strideB;

    const int lr = tid >> 3;             // 0..31 (32 rows per pass)
    const int lc = tid & 7;              // 16B chunk (8 halves) within 128B row

    auto load_stage = [&](int s, int kb) {
        const uint32_t abase = sb + s * STAGE_B;
        const uint32_t bbase = abase + A_STAGE_B;
        const __half* Ag = Abase + (size_t)kb * BK;
        const __half* Bg = Bbase + (size_t)kb * BK;
        #pragma unroll
        for (int i = 0; i < 4; i++) {    // A: 128 rows
            const int row = lr + i * 32;
            cp16(abase + row * (BKP * 2) + lc * 16, Ag + (size_t)row * strideA + lc * 8);
        }
        #pragma unroll
        for (int i = 0; i < 4; i++) {    // B: 128 rows
            const int row = lr + i * 32;
            cp16(bbase + row * (BKP * 2) + lc * 16, Bg + (size_t)row * strideB + lc * 8);
        }
    };

    #pragma unroll
    for (int p = 0; p < STAGES - 1; p++) { load_stage(p, p); CP_COMMIT(); }

    for (int kb = 0; kb < NKB; kb++) {
        CP_WAIT1();                  // stage kb resident
        __syncthreads();             // all warps done computing iter kb-1
        const int jn = kb + (STAGES - 1);
        if (jn < NKB) load_stage(jn % STAGES, jn);
        CP_COMMIT();                 // uniform group numbering (empty at tail)

        const int s = kb % STAGES;
        __half* As = sh + (size_t)s * (STAGE_B / 2);
        __half* Bs = As + (A_STAGE_B / 2);

        #pragma unroll
        for (int ks = 0; ks < BK / 16; ++ks) {
            wmma::fragment<wmma::matrix_a, 16, 16, 16, __half, wmma::row_major> af[WMI];
            wmma::fragment<wmma::matrix_b, 16, 16, 16, __half, wmma::col_major> bf[WNI];
            #pragma unroll
            for (int i = 0; i < WMI; i++)
                wmma::load_matrix_sync(af[i], As + (size_t)(wm0 + i * 16) * BKP + ks * 16, BKP);
            #pragma unroll
            for (int j = 0; j < WNI; j++)
                wmma::load_matrix_sync(bf[j], Bs + (size_t)(wn0 + j * 16) * BKP + ks * 16, BKP);
            #pragma unroll
            for (int i = 0; i < WMI; i++)
                #pragma unroll
                for (int j = 0; j < WNI; j++)
                    wmma::mma_sync(acc[i][j], af[i], bf[j], acc[i][j]);
        }
    }

    // ---- fused epilogue via SMEM scratch (stage memory reused) ----
    __syncthreads();
    float* scr = reinterpret_cast<float*>(smem);
    if (MODE == 3) {
        // col-major scratch: scr[n * EPI_LD + m]
        #pragma unroll
        for (int i = 0; i < WMI; i++)
            #pragma unroll
            for (int j = 0; j < WNI; j++)
                wmma::store_matrix_sync(
                    scr + (size_t)(wn0 + j * 16) * EPI_LD + (wm0 + i * 16),
                    acc[i][j], EPI_LD, wmma::mem_col_major);
    } else {
        // row-major scratch: scr[m * EPI_LD + n]
        #pragma unroll
        for (int i = 0; i < WMI; i++)
            #pragma unroll
            for (int j = 0; j < WNI; j++)
                wmma::store_matrix_sync(
                    scr + (size_t)(wm0 + i * 16) * EPI_LD + (wn0 + j * 16),
                    acc[i][j], EPI_LD, wmma::mem_row_major);
    }
    __syncthreads();

    if (MODE == 1 || MODE == 2) {
        __half* C = reinterpret_cast<__half*>(Cout);
        for (int idx = tid; idx < BM * (BN / 4); idx += NTHR) {
            const int row = idx >> 5;            // BN/4 = 32
            const int c4  = (idx & 31) * 4;
            float4 v = *reinterpret_cast<float4*>(scr + (size_t)row * EPI_LD + c4);
            const float a = __ldg(rv1 + bm0 + row);
            float4 o;
            if (MODE == 1) {
                o = make_float4(v.x * a, v.y * a, v.z * a, v.w * a);
            } else {
                float4 b = *reinterpret_cast<const float4*>(bias + bn0 + c4);
                o = make_float4(fmaxf(v.x + a * b.x, 0.f), fmaxf(v.y + a * b.y, 0.f),
                                fmaxf(v.z + a * b.z, 0.f), fmaxf(v.w + a * b.w, 0.f));
            }
            __half2* q = reinterpret_cast<__half2*>(C + (size_t)(bm0 + row) * Ncols + bn0 + c4);
            q[0] = __floats2half2_rn(o.x, o.y);
            q[1] = __floats2half2_rn(o.z, o.w);
        }
    } else if (MODE == 3) {
        // Cout[n, m] = fp16(rv1[m] * acc[m][n]); output row stride = outStride
        __half* C = reinterpret_cast<__half*>(Cout);
        for (int idx = tid; idx < BN * (BM / 4); idx += NTHR) {
            const int n  = idx >> 5;             // BM/4 = 32
            const int m4 = (idx & 31) * 4;
            float4 v = *reinterpret_cast<float4*>(scr + (size_t)n * EPI_LD + m4);
            float4 w = *reinterpret_cast<const float4*>(rv1 + bm0 + m4);
            float4 o = make_float4(v.x * w.x, v.y * w.y, v.z * w.z, v.w * w.w);
            __half2* q = reinterpret_cast<__half2*>(C + (size_t)(bn0 + n) * outStride + bm0 + m4);
            q[0] = __floats2half2_rn(o.x, o.y);
            q[1] = __floats2half2_rn(o.z, o.w);
        }
    } else { // MODE 4: final fp32 out = relu(rv1[m]*acc + rv2[m]*bias[n])
        float* C = reinterpret_cast<float*>(Cout);
        for (int idx = tid; idx < BM * (BN / 4); idx += NTHR) {
            const int row = idx >> 5;
            const int c4  = (idx & 31) * 4;
            float4 v = *reinterpret_cast<float4*>(scr + (size_t)row * EPI_LD + c4);
            const float s = __ldg(rv1 + bm0 + row);
            const float a = __ldg(rv2 + bm0 + row);
            float4 b = *reinterpret_cast<const float4*>(bias + bn0 + c4);
            float4 o = make_float4(fmaxf(s * v.x + a * b.x, 0.f),
                                   fmaxf(s * v.y + a * b.y, 0.f),
                                   fmaxf(s * v.z + a * b.z, 0.f),
                                   fmaxf(s * v.w + a * b.w, 0.f));
            *reinterpret_cast<float4*>(C + (size_t)(bm0 + row) * Ncols + bn0 + c4) = o;
        }
    }
}

// ---------------- pre kernels ----------------
// Pass 1 (fused): Ah[i,j] = fp16(edge[i,j]); inv[i] = rsqrt(rowsum fp32)
__global__ void convert_rowsum_inv(const float* __restrict__ edge,
                                   __half* __restrict__ Ah, float* __restrict__ inv) {
    const int row = blockIdx.x;
    const float4* p = reinterpret_cast<const float4*>(edge + (size_t)row * N_NODES);
    __half2* q = reinterpret_cast<__half2*>(Ah + (size_t)row * N_NODES);
    float s = 0.f;
    for (int j = threadIdx.x; j < N_NODES / 4; j += blockDim.x) {
        float4 v = p[j];
        q[j * 2]     = __floats2half2_rn(v.x, v.y);
        q[j * 2 + 1] = __floats2half2_rn(v.z, v.w);
        s += (v.x + v.y) + (v.z + v.w);
    }
    #pragma unroll
    for (int o = 16; o > 0; o >>= 1) s += __shfl_down_sync(0xffffffffu, s, o);
    __shared__ float red[8];
    const int lane = threadIdx.x & 31, w = threadIdx.x >> 5;
    if (lane == 0) red[w] = s;
    __syncthreads();
    if (w == 0) {
        s = (lane < 8) ? red[lane] : 0.f;
        #pragma unroll
        for (int o = 4; o > 0; o >>= 1) s += __shfl_down_sync(0xffffffffu, s, o);
        if (lane == 0) inv[row] = (s > 0.f) ? rsqrtf(s) : 0.f;
    }
}

// asum[i] = inv[i] * sum_j Ah[i,j]*inv[j]   (rowsum of effective Â)
__global__ void asum_gemv(const __half* __restrict__ Ah, const float* __restrict__ inv,
                          float* __restrict__ asum) {
    const int row = blockIdx.x;
    const __half2* p = reinterpret_cast<const __half2*>(Ah + (size_t)row * N_NODES);
    const float4* iv = reinterpret_cast<const float4*>(inv);
    float s = 0.f;
    for (int j = threadIdx.x; j < N_NODES / 4; j += blockDim.x) {
        __half2 h01 = p[j * 2], h23 = p[j * 2 + 1];
        float2 f01 = __half22float2(h01), f23 = __half22float2(h23);
        float4 w = iv[j];
        s += f01.x * w.x + f01.y * w.y + f23.x * w.z + f23.y * w.w;
    }
    #pragma unroll
    for (int o = 16; o > 0; o >>= 1) s += __shfl_down_sync(0xffffffffu, s, o);
    __shared__ float red[8];
    const int lane = threadIdx.x & 31, w = threadIdx.x >> 5;
    if (lane == 0) red[w] = s;
    __syncthreads();
    if (w == 0) {
        s = (lane < 8) ? red[lane] : 0.f;
        #pragma unroll
        for (int o = 4; o > 0; o >>= 1) s += __shfl_down_sync(0xffffffffu, s, o);
        if (lane == 0) asum[row] = s * __ldg(inv + row);
    }
}

// generic fp32 -> fp16 (4 per thread)
__global__ void conv_h(const float* __restrict__ in, __half* __restrict__ out) {
    const size_t i = ((size_t)blockIdx.x * blockDim.x + threadIdx.x) * 4;
    float4 v = *reinterpret_cast<const float4*>(in + i);
    __half2* q = reinterpret_cast<__half2*>(out + i);
    q[0] = __floats2half2_rn(v.x, v.y);
    q[1] = __floats2half2_rn(v.z, v.w);
}

// XTh[c, n] = fp16(inv[n] * X[n, c]); X is [N_NODES, IN_C]
__global__ void transpose_x_h(const float* __restrict__ X, const float* __restrict__ inv,
                              __half* __restrict__ XT) {
    __shared__ float t[32][33];
    const int bx = blockIdx.x * 32, by = blockIdx.y * 32;
    const int x = threadIdx.x, y = threadIdx.y;   // 32 x 8
    #pragma unroll
    for (int yy = y; yy < 32; yy += 8)
        t[yy][x] = X[(size_t)(by + yy) * IN_C + bx + x] * __ldg(inv + by + yy);
    __syncthreads();
    #pragma unroll
    for (int yy = y; yy < 32; yy += 8)
        XT[(size_t)(bx + yy) * N_NODES + by + x] = __float2half_rn(t[x][yy]);
}

// ---------------- launch ----------------
extern "C" void kernel_launch(void* const* d_in, const int* in_sizes, int n_in,
                              void* d_out, int out_size) {
    const float* point = (const float*)d_in[0];
    const float* edge  = (const float*)d_in[1];
    const float* W1    = (const float*)d_in[2];
    const float* b1    = (const float*)d_in[3];
    const float* W2    = (const float*)d_in[4];
    const float* b2    = (const float*)d_in[5];
    float* out = (float*)d_out;

    float *inv, *asum;
    __half *Ah, *XTh, *W1h, *W2h, *Gh, *Hh, *OsTh;
    cudaGetSymbolAddress((void**)&inv,  g_inv);
    cudaGetSymbolAddress((void**)&asum, g_asum);
    cudaGetSymbolAddress((void**)&Ah,   g_Ah);
    cudaGetSymbolAddress((void**)&XTh,  g_XTh);
    cudaGetSymbolAddress((void**)&W1h,  g_W1h);
    cudaGetSymbolAddress((void**)&W2h,  g_W2h);
    cudaGetSymbolAddress((void**)&Gh,   g_Gh);
    cudaGetSymbolAddress((void**)&Hh,   g_Hh);
    cudaGetSymbolAddress((void**)&OsTh, g_OsTh);

    cudaFuncSetAttribute(tc_gemm<1>, cudaFuncAttributeMaxDynamicSharedMemorySize, SMEM_GEMM);
    cudaFuncSetAttribute(tc_gemm<2>, cudaFuncAttributeMaxDynamicSharedMemorySize, SMEM_GEMM);
    cudaFuncSetAttribute(tc_gemm<3>, cudaFuncAttributeMaxDynamicSharedMemorySize, SMEM_GEMM);
    cudaFuncSetAttribute(tc_gemm<4>, cudaFuncAttributeMaxDynamicSharedMemorySize, SMEM_GEMM);

    // Side stream for off-critical-path aux work (capture-legal fork/join).
    // Created per call, never destroyed (destroying mid-capture invalidates it).
    cudaStream_t s2;
    cudaStreamCreateWithFlags(&s2, cudaStreamNonBlocking);
    cudaEvent_t ev0, evA, evJ;
    cudaEventCreateWithFlags(&ev0, cudaEventDisableTiming);
    cudaEventCreateWithFlags(&evA, cudaEventDisableTiming);
    cudaEventCreateWithFlags(&evJ, cudaEventDisableTiming);

    cudaEventRecord(ev0, 0);
    cudaStreamWaitEvent(s2, ev0, 0);

    // s2: weight conversions (no deps on edge pipeline)
    conv_h<<<(HID_C * IN_C / 4) / 256, 256, 0, s2>>>(W1, W1h);
    conv_h<<<(OUT_C * HID_C / 4) / 256, 256, 0, s2>>>(W2, W2h);

    // main: edge fp32 -> fp16 raw + rowsum + inv (single pass over edge)
    convert_rowsum_inv<<<N_NODES, 256>>>(edge, Ah, inv);
    cudaEventRecord(evA, 0);                 // Ah + inv ready
    cudaStreamWaitEvent(s2, evA, 0);
    // s2: asum = inv_i * (A_fp16 @ inv) — overlaps transpose_x + GEMM_a
    asum_gemv<<<N_NODES, 256, 0, s2>>>(Ah, inv, asum);
    cudaEventRecord(evJ, s2);                // join marker (asum, W1h, W2h done)

    // main: XTh = fp16(inv_n * X^T)
    transpose_x_h<<<dim3(IN_C / 32, N_NODES / 32), dim3(32, 8)>>>(point, inv, XTh);

    // GEMM_a (MODE 1): Gh = fp16(inv_m * (A @ Xs))  [8192,512]  (256 CTAs)
    tc_gemm<1><<<dim3(IN_C / BN, N_NODES / BM), NTHR, SMEM_GEMM>>>(
        Ah, XTh, Gh, N_NODES, N_NODES, N_NODES, IN_C, 0, inv, nullptr, nullptr);

    // join: GEMM_b needs asum + W1h
    cudaStreamWaitEvent(0, evJ, 0);

    // GEMM_b (MODE 2): Hh = fp16(relu(G@W1^T + asum*b1))  [8192,1024]  (512 CTAs)
    tc_gemm<2><<<dim3(HID_C / BN, N_NODES / BM), NTHR, SMEM_GEMM>>>(
        Gh, W1h, Hh, IN_C, IN_C, IN_C, HID_C, 0, asum, nullptr, b1);

    // GEMM_c (MODE 3): OsTh[n,m] = fp16(inv_m * (H@W2^T)[m,n])  (128 CTAs, full K)
    tc_gemm<3><<<dim3(OUT_C / BN, N_NODES / BM), NTHR, SMEM_GEMM>>>(
        Hh, W2h, OsTh, HID_C, HID_C, HID_C, OUT_C, N_NODES, inv, nullptr, nullptr);

    // GEMM_d (MODE 4): out = relu(inv_m*(A@Os) + asum_m*b2)  fp32  (128 CTAs, full K)
    tc_gemm<4><<<dim3(OUT_C / BN, N_NODES / BM), NTHR, SMEM_GEMM>>>(
        Ah, OsTh, out, N_NODES, N_NODES, N_NODES, OUT_C, 0, inv, asum, b2);
}

// round 17
// speedup vs baseline: 1.0216x; 1.0216x over previous
#include <cuda_runtime.h>
#include <cuda_fp16.h>
#include <mma.h>
#include <cstdint>
#include <cstddef>

using namespace nvcuda;

#define N_NODES 8192
#define IN_C    512
#define HID_C   1024
#define OUT_C   256

// ---------------- scratch (static device arrays; no allocations) ----------------
__device__ float  g_inv [N_NODES];                       // D^{-1/2}
__device__ float  g_asum[N_NODES];                       // rowsum of effective Â
__device__ __half g_Ah  [(size_t)N_NODES * N_NODES];     // fp16(edge), RAW (128 MB)
__device__ __half g_XTh [(size_t)IN_C * N_NODES];        // fp16(inv_n * X^T)
__device__ __half g_W1h [(size_t)HID_C * IN_C];
__device__ __half g_W2h [(size_t)OUT_C * HID_C];
__device__ __half g_Gh  [(size_t)N_NODES * IN_C];        // fp16(Â@X)   (GEMM_a fused out)
__device__ __half g_Hh  [(size_t)N_NODES * HID_C];       // fp16(hidden) (GEMM_b fused out)
__device__ __half g_OsTh[(size_t)OUT_C * N_NODES];       // fp16(inv_m * Os^T)
__device__ float  g_G   [(size_t)2 * N_NODES * OUT_C];   // GEMM_c split-K partials
__device__ float  g_C   [(size_t)2 * N_NODES * OUT_C];   // GEMM_d split-K partials

__device__ __forceinline__ uint32_t smem_u32(const void* p) {
    uint32_t a;
    asm("{ .reg .u64 t; cvta.to.shared.u64 t, %1; cvt.u32.u64 %0, t; }" : "=r"(a) : "l"(p));
    return a;
}
__device__ __forceinline__ void cp16(uint32_t dst, const void* src) {
    asm volatile("cp.async.cg.shared.global [%0], [%1], 16;" :: "r"(dst), "l"(src));
}
#define CP_COMMIT() asm volatile("cp.async.commit_group;" ::: "memory")
#define CP_WAIT1()  asm volatile("cp.async.wait_group 1;" ::: "memory")

// ---- fp16 wmma GEMM: 128x128 block, 256 thr, 8 warps of 32x64, 3-stage cp.async,
// ---- 2 CTAs/SM. Fused epilogue modes:
//   MODE 0: fp32 store (split-K partials)                      -> Cout = float*
//   MODE 1: fp16 store, acc * rowvec[m]                        -> Cout = __half*
//   MODE 2: fp16 store, relu(acc + rowvec[m]*bias[j])          -> Cout = __half*
// C[M,Ncols] = A[M,Klen] @ B[Ncols,Klen]^T, fp16 K-major operands.
// blockIdx.z = split-K slice: koff = z*Klen, Cout += z*csplit (MODE 0 only).
constexpr int NTHR = 256;
constexpr int BM = 128, BN = 128, BK = 64;                // BK halves = 128 B/row
constexpr int BKP = 72;                                   // 144 B/row padded
constexpr int STAGES = 3;
constexpr int A_STAGE_B = BM * BKP * 2;                   // 18432
constexpr int STAGE_B   = (BM + BN) * BKP * 2;            // 36864
constexpr int SMEM_GEMM = STAGES * STAGE_B;               // 110592 (x2 CTAs = 221184/SM)
constexpr int WMI = 2, WNI = 4;                           // 32x64 warp tile
constexpr int EPI_LD = BN + 4;                            // fp32 scratch stride (132)

template <int MODE>
__global__ __launch_bounds__(NTHR, 2) void tc_gemm(
    const __half* __restrict__ A, const __half* __restrict__ B,
    void* __restrict__ Cout, int strideA, int strideB,
    int Klen, int Ncols, size_t csplit,
    const float* __restrict__ rowvec, const float* __restrict__ bias)
{
    extern __shared__ __align__(16) char smem[];
    __half* sh = reinterpret_cast<__half*>(smem);
    const uint32_t sb = smem_u32(smem);

    const int tid  = threadIdx.x;
    const int warp = tid >> 5;
    const int bm0  = blockIdx.y * BM;
    const int bn0  = blockIdx.x * BN;
    const int koff = blockIdx.z * Klen;
    const int wm0 = (warp >> 1) * 32;    // 4 warp rows
    const int wn0 = (warp & 1) * 64;     // 2 warp cols
    const int NKB = Klen / BK;

    wmma::fragment<wmma::accumulator, 16, 16, 16, float> acc[WMI][WNI];
    #pragma unroll
    for (int i = 0; i < WMI; i++)
        #pragma unroll
        for (int j = 0; j < WNI; j++)
            wmma::fill_fragment(acc[i][j], 0.f);

    const __half* Abase = A + (size_t)bm0 * strideA + koff;
    const __half* Bbase = B + (size_t)bn0 * strideB + koff;

    const int lr = tid >> 3;             // 0..31 (32 rows per pass)
    const int lc = tid & 7;              // 16B chunk (8 halves) within 128B row

    auto load_stage = [&](int s, int kb) {
        const uint32_t abase = sb + s * STAGE_B;
        const uint32_t bbase = abase + A_STAGE_B;
        const __half* Ag = Abase + (size_t)kb * BK;
        const __half* Bg = Bbase + (size_t)kb * BK;
        #pragma unroll
        for (int i = 0; i < 4; i++) {    // A: 128 rows
            const int row = lr + i * 32;
            cp16(abase + row * (BKP * 2) + lc * 16, Ag + (size_t)row * strideA + lc * 8);
        }
        #pragma unroll
        for (int i = 0; i < 4; i++) {    // B: 128 rows
            const int row = lr + i * 32;
            cp16(bbase + row * (BKP * 2) + lc * 16, Bg + (size_t)row * strideB + lc * 8);
        }
    };

    #pragma unroll
    for (int p = 0; p < STAGES - 1; p++) { load_stage(p, p); CP_COMMIT(); }

    for (int kb = 0; kb < NKB; kb++) {
        CP_WAIT1();                  // stage kb resident
        __syncthreads();             // all warps done computing iter kb-1
        const int jn = kb + (STAGES - 1);
        if (jn < NKB) load_stage(jn % STAGES, jn);
        CP_COMMIT();                 // uniform group numbering (empty at tail)

        const int s = kb % STAGES;
        __half* As = sh + (size_t)s * (STAGE_B / 2);
        __half* Bs = As + (A_STAGE_B / 2);

        #pragma unroll
        for (int ks = 0; ks < BK / 16; ++ks) {
            wmma::fragment<wmma::matrix_a, 16, 16, 16, __half, wmma::row_major> af[WMI];
            wmma::fragment<wmma::matrix_b, 16, 16, 16, __half, wmma::col_major> bf[WNI];
            #pragma unroll
            for (int i = 0; i < WMI; i++)
                wmma::load_matrix_sync(af[i], As + (size_t)(wm0 + i * 16) * BKP + ks * 16, BKP);
            #pragma unroll
            for (int j = 0; j < WNI; j++)
                wmma::load_matrix_sync(bf[j], Bs + (size_t)(wn0 + j * 16) * BKP + ks * 16, BKP);
            #pragma unroll
            for (int i = 0; i < WMI; i++)
                #pragma unroll
                for (int j = 0; j < WNI; j++)
                    wmma::mma_sync(acc[i][j], af[i], bf[j], acc[i][j]);
        }
    }

    if (MODE == 0) {
        float* C = reinterpret_cast<float*>(Cout) + (size_t)blockIdx.z * csplit;
        #pragma unroll
        for (int i = 0; i < WMI; i++)
            #pragma unroll
            for (int j = 0; j < WNI; j++)
                wmma::store_matrix_sync(
                    &C[(size_t)(bm0 + wm0 + i * 16) * Ncols + (bn0 + wn0 + j * 16)],
                    acc[i][j], Ncols, wmma::mem_row_major);
    } else {
        // fused fp16 epilogue via SMEM scratch (stages no longer needed)
        __syncthreads();
        float* scr = reinterpret_cast<float*>(smem);      // [BM][EPI_LD]
        #pragma unroll
        for (int i = 0; i < WMI; i++)
            #pragma unroll
            for (int j = 0; j < WNI; j++)
                wmma::store_matrix_sync(
                    scr + (size_t)(wm0 + i * 16) * EPI_LD + (wn0 + j * 16),
                    acc[i][j], EPI_LD, wmma::mem_row_major);
        __syncthreads();
        __half* C = reinterpret_cast<__half*>(Cout);
        for (int idx = tid; idx < BM * (BN / 4); idx += NTHR) {
            const int row = idx >> 5;            // BN/4 = 32
            const int c4  = (idx & 31) * 4;
            float4 v = *reinterpret_cast<float4*>(scr + (size_t)row * EPI_LD + c4);
            float4 o;
            const float a = __ldg(rowvec + bm0 + row);
            if (MODE == 1) {
                o = make_float4(v.x * a, v.y * a, v.z * a, v.w * a);
            } else {
                float4 b = *reinterpret_cast<const float4*>(bias + bn0 + c4);
                o = make_float4(fmaxf(v.x + a * b.x, 0.f), fmaxf(v.y + a * b.y, 0.f),
                                fmaxf(v.z + a * b.z, 0.f), fmaxf(v.w + a * b.w, 0.f));
            }
            __half2* q = reinterpret_cast<__half2*>(C + (size_t)(bm0 + row) * Ncols + bn0 + c4);
            q[0] = __floats2half2_rn(o.x, o.y);
            q[1] = __floats2half2_rn(o.z, o.w);
        }
    }
}

// ---------------- pre/post kernels ----------------
// Pass 1 (fused, high-MLP): Ah[i,j] = fp16(edge[i,j]); inv[i] = rsqrt(rowsum fp32)
// 8 elements / thread / iter: 2x float4 loads (independent), 1x uint4 store.
__global__ void convert_rowsum_inv(const float* __restrict__ edge,
                                   __half* __restrict__ Ah, float* __restrict__ inv) {
    const int row = blockIdx.x;
    const float4* p = reinterpret_cast<const float4*>(edge + (size_t)row * N_NODES);
    uint4* q = reinterpret_cast<uint4*>(Ah + (size_t)row * N_NODES);
    float s0 = 0.f, s1 = 0.f;
    #pragma unroll 4
    for (int j = threadIdx.x; j < N_NODES / 8; j += blockDim.x) {
        float4 v0 = p[j * 2];
        float4 v1 = p[j * 2 + 1];
        __half2 h0 = __floats2half2_rn(v0.x, v0.y);
        __half2 h1 = __floats2half2_rn(v0.z, v0.w);
        __half2 h2 = __floats2half2_rn(v1.x, v1.y);
        __half2 h3 = __floats2half2_rn(v1.z, v1.w);
        uint4 w;
        w.x = *reinterpret_cast<uint32_t*>(&h0);
        w.y = *reinterpret_cast<uint32_t*>(&h1);
        w.z = *reinterpret_cast<uint32_t*>(&h2);
        w.w = *reinterpret_cast<uint32_t*>(&h3);
        q[j] = w;
        s0 += (v0.x + v0.y) + (v0.z + v0.w);
        s1 += (v1.x + v1.y) + (v1.z + v1.w);
    }
    float s = s0 + s1;
    #pragma unroll
    for (int o = 16; o > 0; o >>= 1) s += __shfl_down_sync(0xffffffffu, s, o);
    __shared__ float red[8];
    const int lane = threadIdx.x & 31, w = threadIdx.x >> 5;
    if (lane == 0) red[w] = s;
    __syncthreads();
    if (w == 0) {
        s = (lane < 8) ? red[lane] : 0.f;
        #pragma unroll
        for (int o = 4; o > 0; o >>= 1) s += __shfl_down_sync(0xffffffffu, s, o);
        if (lane == 0) inv[row] = (s > 0.f) ? rsqrtf(s) : 0.f;
    }
}

// asum[i] = inv[i] * sum_j Ah[i,j]*inv[j]  — 8 halves (uint4) + 2 float4 per iter
__global__ void asum_gemv(const __half* __restrict__ Ah, const float* __restrict__ inv,
                          float* __restrict__ asum) {
    const int row = blockIdx.x;
    const uint4* p = reinterpret_cast<const uint4*>(Ah + (size_t)row * N_NODES);
    const float4* iv = reinterpret_cast<const float4*>(inv);
    float s0 = 0.f, s1 = 0.f;
    #pragma unroll 4
    for (int j = threadIdx.x; j < N_NODES / 8; j += blockDim.x) {
        uint4 hv = p[j];
        float4 w0 = iv[j * 2];
        float4 w1 = iv[j * 2 + 1];
        float2 f0 = __half22float2(*reinterpret_cast<__half2*>(&hv.x));
        float2 f1 = __half22float2(*reinterpret_cast<__half2*>(&hv.y));
        float2 f2 = __half22float2(*reinterpret_cast<__half2*>(&hv.z));
        float2 f3 = __half22float2(*reinterpret_cast<__half2*>(&hv.w));
        s0 += f0.x * w0.x + f0.y * w0.y + f1.x * w0.z + f1.y * w0.w;
        s1 += f2.x * w1.x + f2.y * w1.y + f3.x * w1.z + f3.y * w1.w;
    }
    float s = s0 + s1;
    #pragma unroll
    for (int o = 16; o > 0; o >>= 1) s += __shfl_down_sync(0xffffffffu, s, o);
    __shared__ float red[8];
    const int lane = threadIdx.x & 31, w = threadIdx.x >> 5;
    if (lane == 0) red[w] = s;
    __syncthreads();
    if (w == 0) {
        s = (lane < 8) ? red[lane] : 0.f;
        #pragma unroll
        for (int o = 4; o > 0; o >>= 1) s += __shfl_down_sync(0xffffffffu, s, o);
        if (lane == 0) asum[row] = s * __ldg(inv + row);
    }
}

// generic fp32 -> fp16 (4 per thread)
__global__ void conv_h(const float* __restrict__ in, __half* __restrict__ out) {
    const size_t i = ((size_t)blockIdx.x * blockDim.x + threadIdx.x) * 4;
    float4 v = *reinterpret_cast<const float4*>(in + i);
    __half2* q = reinterpret_cast<__half2*>(out + i);
    q[0] = __floats2half2_rn(v.x, v.y);
    q[1] = __floats2half2_rn(v.z, v.w);
}

// XTh[c, n] = fp16(inv[n] * X[n, c]); X is [N_NODES, IN_C]
__global__ void transpose_x_h(const float* __restrict__ X, const float* __restrict__ inv,
                              __half* __restrict__ XT) {
    __shared__ float t[32][33];
    const int bx = blockIdx.x * 32, by = blockIdx.y * 32;
    const int x = threadIdx.x, y = threadIdx.y;   // 32 x 8
    #pragma unroll
    for (int yy = y; yy < 32; yy += 8)
        t[yy][x] = X[(size_t)(by + yy) * IN_C + bx + x] * __ldg(inv + by + yy);
    __syncthreads();
    #pragma unroll
    for (int yy = y; yy < 32; yy += 8)
        XT[(size_t)(bx + yy) * N_NODES + by + x] = __float2half_rn(t[x][yy]);
}

// outT[n, m] = fp16(inv[m] * (D0[m,n] + D1[m,n])); D is [M, Ncols]
__global__ void epi_transpose_sum2_h(const float* __restrict__ D0, const float* __restrict__ D1,
                                     const float* __restrict__ inv,
                                     __half* __restrict__ outT, int M, int Ncols) {
    __shared__ float t[32][33];
    const int bx = blockIdx.x * 32, by = blockIdx.y * 32;
    const int x = threadIdx.x, y = threadIdx.y;   // 32 x 8
    #pragma unroll
    for (int yy = y; yy < 32; yy += 8) {
        const size_t idx = (size_t)(by + yy) * Ncols + bx + x;
        t[yy][x] = (D0[idx] + D1[idx]) * __ldg(inv + by + yy);
    }
    __syncthreads();
    #pragma unroll
    for (int yy = y; yy < 32; yy += 8)
        outT[(size_t)(bx + yy) * M + by + x] = __float2half_rn(t[x][yy]);
}

// out[m,j] = relu(inv[m]*(C0+C1) + asum[m]*b2[j])  (final, fp32)
__global__ void epi_relu_biasrow_sum2(const float* __restrict__ C0, const float* __restrict__ C1,
                                      const float* __restrict__ inv, const float* __restrict__ asum,
                                      const float* __restrict__ bias,
                                      float* __restrict__ out, int Ncols) {
    const size_t i = (size_t)blockIdx.x * blockDim.x + threadIdx.x;
    const int m  = (int)(i / (Ncols / 4));
    const int j4 = (int)(i % (Ncols / 4)) * 4;
    const float a = __ldg(asum + m);
    const float s = __ldg(inv + m);
    const size_t off = (size_t)m * Ncols + j4;
    float4 c0 = *reinterpret_cast<const float4*>(C0 + off);
    float4 c1 = *reinterpret_cast<const float4*>(C1 + off);
    float4 b  = *reinterpret_cast<const float4*>(bias + j4);
    float4 o = make_float4(fmaxf((c0.x + c1.x) * s + a * b.x, 0.f),
                           fmaxf((c0.y + c1.y) * s + a * b.y, 0.f),
                           fmaxf((c0.z + c1.z) * s + a * b.z, 0.f),
                           fmaxf((c0.w + c1.w) * s + a * b.w, 0.f));
    *reinterpret_cast<float4*>(out + off) = o;
}

// ---------------- launch ----------------
extern "C" void kernel_launch(void* const* d_in, const int* in_sizes, int n_in,
                              void* d_out, int out_size) {
    const float* point = (const float*)d_in[0];
    const float* edge  = (const float*)d_in[1];
    const float* W1    = (const float*)d_in[2];
    const float* b1    = (const float*)d_in[3];
    const float* W2    = (const float*)d_in[4];
    const float* b2    = (const float*)d_in[5];
    float* out = (float*)d_out;

    float *inv, *asum, *G, *C;
    __half *Ah, *XTh, *W1h, *W2h, *Gh, *Hh, *OsTh;
    cudaGetSymbolAddress((void**)&inv,  g_inv);
    cudaGetSymbolAddress((void**)&asum, g_asum);
    cudaGetSymbolAddress((void**)&Ah,   g_Ah);
    cudaGetSymbolAddress((void**)&XTh,  g_XTh);
    cudaGetSymbolAddress((void**)&W1h,  g_W1h);
    cudaGetSymbolAddress((void**)&W2h,  g_W2h);
    cudaGetSymbolAddress((void**)&Gh,   g_Gh);
    cudaGetSymbolAddress((void**)&Hh,   g_Hh);
    cudaGetSymbolAddress((void**)&OsTh, g_OsTh);
    cudaGetSymbolAddress((void**)&G,    g_G);
    cudaGetSymbolAddress((void**)&C,    g_C);

    cudaFuncSetAttribute(tc_gemm<0>, cudaFuncAttributeMaxDynamicSharedMemorySize, SMEM_GEMM);
    cudaFuncSetAttribute(tc_gemm<1>, cudaFuncAttributeMaxDynamicSharedMemorySize, SMEM_GEMM);
    cudaFuncSetAttribute(tc_gemm<2>, cudaFuncAttributeMaxDynamicSharedMemorySize, SMEM_GEMM);

    const size_t SPLIT = (size_t)N_NODES * OUT_C;   // split-K partial buffer stride

    // Side stream for off-critical-path aux work (capture-legal fork/join).
    // Created per call, never destroyed (destroying mid-capture invalidates it).
    cudaStream_t s2;
    cudaStreamCreateWithFlags(&s2, cudaStreamNonBlocking);
    cudaEvent_t ev0, evA, evJ;
    cudaEventCreateWithFlags(&ev0, cudaEventDisableTiming);
    cudaEventCreateWithFlags(&evA, cudaEventDisableTiming);
    cudaEventCreateWithFlags(&evJ, cudaEventDisableTiming);

    cudaEventRecord(ev0, 0);
    cudaStreamWaitEvent(s2, ev0, 0);

    // s2: weight conversions (no deps on edge pipeline)
    conv_h<<<(HID_C * IN_C / 4) / 256, 256, 0, s2>>>(W1, W1h);
    conv_h<<<(OUT_C * HID_C / 4) / 256, 256, 0, s2>>>(W2, W2h);

    // main: edge fp32 -> fp16 raw + rowsum + inv (single high-MLP pass over edge)
    convert_rowsum_inv<<<N_NODES, 256>>>(edge, Ah, inv);
    cudaEventRecord(evA, 0);                 // Ah + inv ready
    cudaStreamWaitEvent(s2, evA, 0);
    // s2: asum = inv_i * (A_fp16 @ inv) — overlaps transpose_x + GEMM_a
    asum_gemv<<<N_NODES, 256, 0, s2>>>(Ah, inv, asum);
    cudaEventRecord(evJ, s2);                // join marker (asum, W1h, W2h done)

    // main: XTh = fp16(inv_n * X^T)
    transpose_x_h<<<dim3(IN_C / 32, N_NODES / 32), dim3(32, 8)>>>(point, inv, XTh);

    // GEMM_a (MODE 1): Gh = fp16(inv_m * (A @ Xs))  [8192,512]  (256 CTAs)
    tc_gemm<1><<<dim3(IN_C / BN, N_NODES / BM, 1), NTHR, SMEM_GEMM>>>(
        Ah, XTh, Gh, N_NODES, N_NODES, N_NODES, IN_C, 0, inv, nullptr);

    // join: GEMM_b needs asum + W1h
    cudaStreamWaitEvent(0, evJ, 0);

    // GEMM_b (MODE 2): Hh = fp16(relu(G@W1^T + asum*b1))  [8192,1024]  (512 CTAs)
    tc_gemm<2><<<dim3(HID_C / BN, N_NODES / BM, 1), NTHR, SMEM_GEMM>>>(
        Gh, W1h, Hh, IN_C, IN_C, IN_C, HID_C, 0, asum, b1);

    // GEMM_c (MODE 0, split-K=2): D0,D1 = H@W2^T partials  [8192,256]  (256 CTAs)
    tc_gemm<0><<<dim3(OUT_C / BN, N_NODES / BM, 2), NTHR, SMEM_GEMM>>>(
        Hh, W2h, G, HID_C, HID_C, HID_C / 2, OUT_C, SPLIT, nullptr, nullptr);
    // OsTh = fp16(inv_m * (D0+D1)^T)
    epi_transpose_sum2_h<<<dim3(OUT_C / 32, N_NODES / 32), dim3(32, 8)>>>(
        G, G + SPLIT, inv, OsTh, N_NODES, OUT_C);

    // GEMM_d (MODE 0, split-K=2): C0,C1 = A@Os partials  [8192,256]  (256 CTAs)
    tc_gemm<0><<<dim3(OUT_C / BN, N_NODES / BM, 2), NTHR, SMEM_GEMM>>>(
        Ah, OsTh, C, N_NODES, N_NODES, N_NODES / 2, OUT_C, SPLIT, nullptr, nullptr);
    // out = relu(inv_m*(C0+C1) + asum*b2)
    epi_relu_biasrow_sum2<<<(N_NODES * OUT_C / 4) / 256, 256>>>(
        C, C + SPLIT, inv, asum, b2, out, OUT_C);
}